// round 1
// baseline (speedup 1.0000x reference)
#include <cuda_runtime.h>
#include <math.h>

#define N_IMG  64
#define S_TOK  2602
#define NPATCH 2601
#define E_DIM  128
#define E3     384
#define KPAD   76      // 75 padded to multiple of 4

// ---------------- scratch (device globals; no runtime allocation) ----------------
__device__ float g_pe   [S_TOK * E_DIM];                    // positional embeddings
__device__ float g_x    [N_IMG * S_TOK * E_DIM];            // tokens after embed+pe
__device__ float g_qkv  [(size_t)N_IMG * S_TOK * E3];       // qkv
__device__ float g_o    [N_IMG * S_TOK * E_DIM];            // attention output
__device__ float g_lmwT [KPAD * E_DIM];                     // lm_w^T padded (76x128)
__device__ float g_winT [E_DIM * E3];                       // w_in^T  (128x384)
__device__ float g_woutT[E_DIM * E_DIM];                    // w_out^T (128x128)
__device__ float g_pooled[N_IMG * E_DIM];                   // pooled accumulator

// ---------------- small prep kernels ----------------
__global__ void k_prep(const float* __restrict__ lm_w,
                       const float* __restrict__ w_in,
                       const float* __restrict__ w_out) {
    int t = blockIdx.x * blockDim.x + threadIdx.x;
    int n = gridDim.x * blockDim.x;
    for (int i = t; i < KPAD * E_DIM; i += n) {
        int k = i / E_DIM, e = i % E_DIM;
        g_lmwT[i] = (k < 75) ? lm_w[e * 75 + k] : 0.0f;
    }
    for (int i = t; i < E_DIM * E3; i += n) {
        int k = i / E3, c = i % E3;
        g_winT[i] = w_in[c * E_DIM + k];
    }
    for (int i = t; i < E_DIM * E_DIM; i += n) {
        int k = i / E_DIM, c = i % E_DIM;
        g_woutT[i] = w_out[c * E_DIM + k];
    }
}

__global__ void k_pe() {
    int s = blockIdx.x, e = threadIdx.x;
    int je = e & ~1;
    double scale = exp(-((double)je / 128.0) * log(10000.0));
    double ang = (double)s * scale;
    double v = (e & 1) ? cos(ang) : sin(ang);
    g_pe[s * E_DIM + e] = (float)v;
}

__global__ void k_clszero(const float* __restrict__ cls_tok) {
    int tid = threadIdx.x;
    if (blockIdx.x < N_IMG) {
        int b = blockIdx.x;
        // pe(0,e): angle 0 -> sin=0 (even e), cos=1 (odd e)
        g_x[(b * S_TOK) * E_DIM + tid] = cls_tok[tid] + ((tid & 1) ? 1.0f : 0.0f);
    } else {
        for (int i = tid; i < N_IMG * E_DIM; i += blockDim.x) g_pooled[i] = 0.0f;
    }
}

// ---------------- fused patchify + linear embed ----------------
// per block: one image, 64 patches x 128 out dims, K=75(->76)
__global__ __launch_bounds__(256) void k_embed(const float* __restrict__ images,
                                               const float* __restrict__ lm_b) {
    extern __shared__ float sm[];
    float* As = sm;               // [64][76]
    float* Bs = sm + 64 * KPAD;   // [76][128]
    const int b  = blockIdx.y;
    const int p0 = blockIdx.x * 64;
    const int tid = threadIdx.x;

    for (int i = tid; i < KPAD * E_DIM; i += 256) Bs[i] = g_lmwT[i];

    for (int i = tid; i < 64 * KPAD; i += 256) {
        int m = i / KPAD, k = i % KPAD;
        int p = p0 + m;
        float v = 0.0f;
        if (k < 75 && p < NPATCH) {
            int c = k / 25, r = k % 25, ph = r / 5, pw = r % 5;
            int ii = p / 51, jj = p % 51;
            v = images[((b * 3 + c) * 255 + (ii * 5 + ph)) * 255 + (jj * 5 + pw)];
        }
        As[i] = v;
    }
    __syncthreads();

    const int tx = tid & 15, ty = tid >> 4;
    float acc[4][8];
    #pragma unroll
    for (int i = 0; i < 4; i++)
        #pragma unroll
        for (int j = 0; j < 8; j++) acc[i][j] = 0.0f;

    #pragma unroll 1
    for (int k = 0; k < KPAD; k += 4) {
        float4 av[4];
        #pragma unroll
        for (int i = 0; i < 4; i++)
            av[i] = *(const float4*)&As[(ty * 4 + i) * KPAD + k];
        #pragma unroll
        for (int kk = 0; kk < 4; kk++) {
            float4 b0 = *(const float4*)&Bs[(k + kk) * E_DIM + tx * 4];
            float4 b1 = *(const float4*)&Bs[(k + kk) * E_DIM + 64 + tx * 4];
            float bb[8] = {b0.x, b0.y, b0.z, b0.w, b1.x, b1.y, b1.z, b1.w};
            #pragma unroll
            for (int i = 0; i < 4; i++) {
                float a = ((const float*)&av[i])[kk];
                #pragma unroll
                for (int j = 0; j < 8; j++) acc[i][j] += a * bb[j];
            }
        }
    }

    #pragma unroll
    for (int i = 0; i < 4; i++) {
        int p = p0 + ty * 4 + i;
        if (p >= NPATCH) continue;
        int s = 1 + p;
        size_t base = ((size_t)b * S_TOK + s) * E_DIM;
        #pragma unroll
        for (int half = 0; half < 2; half++) {
            int col = half * 64 + tx * 4;
            float4 o;
            o.x = acc[i][half*4+0] + lm_b[col+0] + g_pe[s * E_DIM + col + 0];
            o.y = acc[i][half*4+1] + lm_b[col+1] + g_pe[s * E_DIM + col + 1];
            o.z = acc[i][half*4+2] + lm_b[col+2] + g_pe[s * E_DIM + col + 2];
            o.w = acc[i][half*4+3] + lm_b[col+3] + g_pe[s * E_DIM + col + 3];
            *(float4*)&g_x[base + col] = o;
        }
    }
}

// ---------------- QKV GEMM: (166528 x 128) @ (128 x 384) + b_in ----------------
#define ASTRIDE 132
__global__ __launch_bounds__(256) void k_qkvg(const float* __restrict__ b_in) {
    extern __shared__ float sm[];
    float* As = sm;                    // [128][132]
    float* Bs = sm + 128 * ASTRIDE;    // [128][128]
    const int m0 = blockIdx.x * 128;
    const int n0 = blockIdx.y * 128;
    const int tid = threadIdx.x;

    for (int i = tid; i < 128 * 32; i += 256) {
        int m = i >> 5, k4 = (i & 31) << 2;
        *(float4*)&As[m * ASTRIDE + k4] = *(const float4*)&g_x[(size_t)(m0 + m) * E_DIM + k4];
    }
    for (int i = tid; i < 128 * 32; i += 256) {
        int k = i >> 5, n4 = (i & 31) << 2;
        *(float4*)&Bs[k * 128 + n4] = *(const float4*)&g_winT[k * E3 + n0 + n4];
    }
    __syncthreads();

    const int tx = tid & 15, ty = tid >> 4;
    float acc[8][8];
    #pragma unroll
    for (int i = 0; i < 8; i++)
        #pragma unroll
        for (int j = 0; j < 8; j++) acc[i][j] = 0.0f;

    #pragma unroll 1
    for (int k = 0; k < 128; k += 4) {
        float4 a0[4], a1[4];
        #pragma unroll
        for (int i = 0; i < 4; i++) {
            a0[i] = *(const float4*)&As[(ty * 4 + i) * ASTRIDE + k];
            a1[i] = *(const float4*)&As[(64 + ty * 4 + i) * ASTRIDE + k];
        }
        #pragma unroll
        for (int kk = 0; kk < 4; kk++) {
            float4 b0 = *(const float4*)&Bs[(k + kk) * 128 + tx * 4];
            float4 b1 = *(const float4*)&Bs[(k + kk) * 128 + 64 + tx * 4];
            float bb[8] = {b0.x, b0.y, b0.z, b0.w, b1.x, b1.y, b1.z, b1.w};
            #pragma unroll
            for (int i = 0; i < 8; i++) {
                float a = (i < 4) ? ((const float*)&a0[i])[kk]
                                  : ((const float*)&a1[i - 4])[kk];
                #pragma unroll
                for (int j = 0; j < 8; j++) acc[i][j] += a * bb[j];
            }
        }
    }

    #pragma unroll
    for (int i = 0; i < 8; i++) {
        int row = m0 + ((i < 4) ? (ty * 4 + i) : (64 + ty * 4 + i - 4));
        size_t base = (size_t)row * E3 + n0;
        #pragma unroll
        for (int half = 0; half < 2; half++) {
            int col = half * 64 + tx * 4;
            float4 o;
            o.x = acc[i][half*4+0] + b_in[n0 + col + 0];
            o.y = acc[i][half*4+1] + b_in[n0 + col + 1];
            o.z = acc[i][half*4+2] + b_in[n0 + col + 2];
            o.w = acc[i][half*4+3] + b_in[n0 + col + 3];
            *(float4*)&g_qkv[base + col] = o;
        }
    }
}

// ---------------- attention across images, per (token s, head h) ----------------
__global__ __launch_bounds__(512) void k_attn() {
    extern __shared__ float sm[];   // [64][384] qkv for this token
    const int s = blockIdx.x, tid = threadIdx.x;

    for (int i = tid; i < 64 * 96; i += 512) {
        int b = i / 96, j = i % 96;
        ((float4*)sm)[i] = *(const float4*)&g_qkv[((size_t)b * S_TOK + s) * E3 + j * 4];
    }
    __syncthreads();

    const int h = tid >> 6, l = tid & 63;
    float q[16];
    {
        const float* qp = &sm[l * E3 + h * 16];
        #pragma unroll
        for (int d = 0; d < 16; d++) q[d] = qp[d] * 0.25f;   // 1/sqrt(16)
    }
    float sc[64];
    float mx = -1e30f;
    #pragma unroll
    for (int m = 0; m < 64; m++) {
        const float* kp = &sm[m * E3 + 128 + h * 16];
        float d0 = 0.f, d1 = 0.f, d2 = 0.f, d3 = 0.f;
        #pragma unroll
        for (int d = 0; d < 4; d++) {
            d0 += q[d]      * kp[d];
            d1 += q[4 + d]  * kp[4 + d];
            d2 += q[8 + d]  * kp[8 + d];
            d3 += q[12 + d] * kp[12 + d];
        }
        sc[m] = (d0 + d1) + (d2 + d3);
        mx = fmaxf(mx, sc[m]);
    }
    float sum = 0.f;
    #pragma unroll
    for (int m = 0; m < 64; m++) { sc[m] = expf(sc[m] - mx); sum += sc[m]; }
    float o[16];
    #pragma unroll
    for (int d = 0; d < 16; d++) o[d] = 0.f;
    #pragma unroll
    for (int m = 0; m < 64; m++) {
        const float w = sc[m];
        const float* vp = &sm[m * E3 + 256 + h * 16];
        #pragma unroll
        for (int d = 0; d < 16; d++) o[d] += w * vp[d];
    }
    const float inv = 1.0f / sum;
    size_t base = ((size_t)l * S_TOK + s) * E_DIM + h * 16;
    #pragma unroll
    for (int d4 = 0; d4 < 4; d4++) {
        float4 ov;
        ov.x = o[d4*4+0]*inv; ov.y = o[d4*4+1]*inv;
        ov.z = o[d4*4+2]*inv; ov.w = o[d4*4+3]*inv;
        *(float4*)&g_o[base + d4 * 4] = ov;
    }
}

// ---------------- out-proj GEMM + LayerNorm + pooled accumulation ----------------
__global__ __launch_bounds__(256) void k_outg(const float* __restrict__ b_out,
                                              const float* __restrict__ ln_g,
                                              const float* __restrict__ ln_b) {
    extern __shared__ float sm[];
    float* As   = sm;                              // [128][132], reused as C tile
    float* Bs   = sm + 128 * ASTRIDE;              // [128][128]
    float* sMu  = sm + 128 * ASTRIDE + 128 * 128;  // [128]
    float* sRsd = sMu + 128;                       // [128]
    const int m0 = blockIdx.x * 128;
    const int tid = threadIdx.x;

    for (int i = tid; i < 128 * 32; i += 256) {
        int m = i >> 5, k4 = (i & 31) << 2;
        *(float4*)&As[m * ASTRIDE + k4] = *(const float4*)&g_o[(size_t)(m0 + m) * E_DIM + k4];
    }
    for (int i = tid; i < 128 * 32; i += 256) {
        int k = i >> 5, n4 = (i & 31) << 2;
        *(float4*)&Bs[k * 128 + n4] = *(const float4*)&g_woutT[k * E_DIM + n4];
    }
    __syncthreads();

    const int tx = tid & 15, ty = tid >> 4;
    float acc[8][8];
    #pragma unroll
    for (int i = 0; i < 8; i++)
        #pragma unroll
        for (int j = 0; j < 8; j++) acc[i][j] = 0.0f;

    #pragma unroll 1
    for (int k = 0; k < 128; k += 4) {
        float4 a0[4], a1[4];
        #pragma unroll
        for (int i = 0; i < 4; i++) {
            a0[i] = *(const float4*)&As[(ty * 4 + i) * ASTRIDE + k];
            a1[i] = *(const float4*)&As[(64 + ty * 4 + i) * ASTRIDE + k];
        }
        #pragma unroll
        for (int kk = 0; kk < 4; kk++) {
            float4 b0 = *(const float4*)&Bs[(k + kk) * 128 + tx * 4];
            float4 b1 = *(const float4*)&Bs[(k + kk) * 128 + 64 + tx * 4];
            float bb[8] = {b0.x, b0.y, b0.z, b0.w, b1.x, b1.y, b1.z, b1.w};
            #pragma unroll
            for (int i = 0; i < 8; i++) {
                float a = (i < 4) ? ((const float*)&a0[i])[kk]
                                  : ((const float*)&a1[i - 4])[kk];
                #pragma unroll
                for (int j = 0; j < 8; j++) acc[i][j] += a * bb[j];
            }
        }
    }
    __syncthreads();   // done reading As, reuse it as C tile

    #pragma unroll
    for (int i = 0; i < 8; i++) {
        int r = (i < 4) ? (ty * 4 + i) : (64 + ty * 4 + i - 4);
        #pragma unroll
        for (int half = 0; half < 2; half++) {
            int col = half * 64 + tx * 4;
            #pragma unroll
            for (int j = 0; j < 4; j++)
                As[r * ASTRIDE + col + j] = acc[i][half * 4 + j] + b_out[col + j];
        }
    }
    __syncthreads();

    if (tid < 128) {
        const float* row = &As[tid * ASTRIDE];
        float s1 = 0.f;
        #pragma unroll 8
        for (int j = 0; j < 128; j++) s1 += row[j];
        float mu = s1 * (1.0f / 128.0f);
        float s2 = 0.f;
        #pragma unroll 8
        for (int j = 0; j < 128; j++) { float d = row[j] - mu; s2 += d * d; }
        sMu[tid] = mu;
        sRsd[tid] = rsqrtf(s2 * (1.0f / 128.0f) + 1e-5f);
    }
    __syncthreads();

    // pooled accumulation: thread = (column, row-half); rows sorted so image id
    // changes at most once inside the block.
    {
        int col = tid & 127;
        int r = (tid >> 7) * 64;
        float gg = ln_g[col], bb = ln_b[col];
        int b0 = (m0 + r) / S_TOK;
        int boundary = (b0 + 1) * S_TOK - m0;  // first local row of next image
        float a0 = 0.f, a1 = 0.f;
        #pragma unroll 4
        for (int t = 0; t < 64; t++, r++) {
            float v = (As[r * ASTRIDE + col] - sMu[r]) * sRsd[r] * gg + bb;
            if (r < boundary) a0 += v; else a1 += v;
        }
        atomicAdd(&g_pooled[b0 * E_DIM + col], a0);
        if (a1 != 0.f || ((tid >> 7) * 64 + 63) >= boundary)
            if (b0 + 1 < N_IMG) atomicAdd(&g_pooled[(b0 + 1) * E_DIM + col], a1);
    }
}

// ---------------- classifier head ----------------
__global__ void k_head(const float* __restrict__ out_w,
                       const float* __restrict__ out_b,
                       float* __restrict__ out) {
    int b = blockIdx.x, tid = threadIdx.x;
    __shared__ float red[3][4];
    float p = g_pooled[b * E_DIM + tid] * (1.0f / (float)S_TOK);
    int lane = tid & 31, w = tid >> 5;
    #pragma unroll
    for (int c = 0; c < 3; c++) {
        float v = p * out_w[c * E_DIM + tid];
        #pragma unroll
        for (int off = 16; off; off >>= 1) v += __shfl_xor_sync(0xffffffffu, v, off);
        if (lane == 0) red[c][w] = v;
    }
    __syncthreads();
    if (tid < 3)
        out[b * 3 + tid] = red[tid][0] + red[tid][1] + red[tid][2] + red[tid][3] + out_b[tid];
}

// ---------------- launch ----------------
extern "C" void kernel_launch(void* const* d_in, const int* in_sizes, int n_in,
                              void* d_out, int out_size) {
    const float* images  = (const float*)d_in[0];
    const float* lm_w    = (const float*)d_in[1];
    const float* lm_b    = (const float*)d_in[2];
    const float* cls_tok = (const float*)d_in[3];
    const float* w_in    = (const float*)d_in[4];
    const float* b_in    = (const float*)d_in[5];
    const float* w_out   = (const float*)d_in[6];
    const float* b_out   = (const float*)d_in[7];
    const float* ln_g    = (const float*)d_in[8];
    const float* ln_b    = (const float*)d_in[9];
    const float* out_w   = (const float*)d_in[10];
    const float* out_b   = (const float*)d_in[11];
    float* out = (float*)d_out;

    const int SMEM_EMBED = (64 * KPAD + KPAD * E_DIM) * 4;
    const int SMEM_GEMM  = (128 * ASTRIDE + 128 * 128) * 4;
    const int SMEM_OUT   = SMEM_GEMM + 256 * 4;
    const int SMEM_ATTN  = 64 * E3 * 4;

    cudaFuncSetAttribute(k_embed, cudaFuncAttributeMaxDynamicSharedMemorySize, SMEM_EMBED);
    cudaFuncSetAttribute(k_qkvg,  cudaFuncAttributeMaxDynamicSharedMemorySize, SMEM_GEMM);
    cudaFuncSetAttribute(k_outg,  cudaFuncAttributeMaxDynamicSharedMemorySize, SMEM_OUT);
    cudaFuncSetAttribute(k_attn,  cudaFuncAttributeMaxDynamicSharedMemorySize, SMEM_ATTN);

    k_prep<<<96, 256>>>(lm_w, w_in, w_out);
    k_pe<<<S_TOK, 128>>>();
    k_clszero<<<N_IMG + 1, 128>>>(cls_tok);
    k_embed<<<dim3(41, N_IMG), 256, SMEM_EMBED>>>(images, lm_b);
    k_qkvg<<<dim3(1301, 3), 256, SMEM_GEMM>>>(b_in);
    k_attn<<<S_TOK, 512, SMEM_ATTN>>>();
    k_outg<<<1301, 256, SMEM_OUT>>>(b_out, ln_g, ln_b);
    k_head<<<N_IMG, 128>>>(out_w, out_b, out);
}

// round 4
// speedup vs baseline: 1.5315x; 1.5315x over previous
#include <cuda_runtime.h>
#include <cuda_bf16.h>
#include <mma.h>
#include <math.h>
#include <stdint.h>

using namespace nvcuda;

#define N_IMG  64
#define S_TOK  2602
#define NPATCH 2601
#define E_DIM  128
#define E3     384
#define KPAD   76
#define NROWS  (N_IMG * S_TOK)     // 166528 = 1301*128
#define ASTR   136                 // bf16 smem row stride (pad 8)

extern __shared__ char smraw[];

// ======================= scratch =======================
__device__ __align__(16) __nv_bfloat16 g_x_h[(size_t)NROWS * E_DIM];
__device__ __align__(16) __nv_bfloat16 g_x_l[(size_t)NROWS * E_DIM];
__device__ __align__(16) float         g_qkv[(size_t)NROWS * E3];
__device__ __align__(16) __nv_bfloat16 g_o_h[(size_t)NROWS * E_DIM];
__device__ __align__(16) __nv_bfloat16 g_o_l[(size_t)NROWS * E_DIM];
__device__ __align__(16) __nv_bfloat16 g_win_h[E3 * E_DIM];   // [n][k]
__device__ __align__(16) __nv_bfloat16 g_win_l[E3 * E_DIM];
__device__ __align__(16) __nv_bfloat16 g_wout_h[E_DIM * E_DIM];
__device__ __align__(16) __nv_bfloat16 g_wout_l[E_DIM * E_DIM];
__device__ float g_pe[S_TOK * E_DIM];
__device__ float g_lmwT[KPAD * E_DIM];
__device__ float g_pooled[N_IMG * E_DIM];

__device__ __forceinline__ void split2(float x, float y, __nv_bfloat162* hp, __nv_bfloat162* lp) {
    __nv_bfloat162 h = __float22bfloat162_rn(make_float2(x, y));
    float rx = x - __low2float(h), ry = y - __high2float(h);
    *hp = h;
    *lp = __float22bfloat162_rn(make_float2(rx, ry));
}

// copy a 128-row x 128-col bf16 tile (row-major, src stride 128) into smem stride ASTR
__device__ __forceinline__ void stage136(__nv_bfloat16* dst, const __nv_bfloat16* src, int tid) {
    #pragma unroll
    for (int it = 0; it < 8; ++it) {
        int i = tid + it * 256;
        int row = i >> 4, c = i & 15;
        *(uint4*)&dst[row * ASTR + c * 8] = *(const uint4*)&src[row * 128 + c * 8];
    }
}

// ======================= prep kernels =======================
__global__ void k_prep(const float* __restrict__ lm_w,
                       const float* __restrict__ w_in,
                       const float* __restrict__ w_out) {
    int t = blockIdx.x * blockDim.x + threadIdx.x;
    int n = gridDim.x * blockDim.x;
    for (int i = t; i < KPAD * E_DIM; i += n) {
        int k = i / E_DIM, e = i % E_DIM;
        g_lmwT[i] = (k < 75) ? lm_w[e * 75 + k] : 0.0f;
    }
    for (int i = t; i < E3 * E_DIM; i += n) {
        float v = w_in[i];
        __nv_bfloat16 h = __float2bfloat16(v);
        g_win_h[i] = h;
        g_win_l[i] = __float2bfloat16(v - __bfloat162float(h));
    }
    for (int i = t; i < E_DIM * E_DIM; i += n) {
        float v = w_out[i];
        __nv_bfloat16 h = __float2bfloat16(v);
        g_wout_h[i] = h;
        g_wout_l[i] = __float2bfloat16(v - __bfloat162float(h));
    }
}

__global__ void k_pe() {
    int s = blockIdx.x, e = threadIdx.x;
    int je = e & ~1;
    double scale = exp(-((double)je / 128.0) * log(10000.0));
    double ang = (double)s * scale;
    double v = (e & 1) ? cos(ang) : sin(ang);
    g_pe[s * E_DIM + e] = (float)v;
}

__global__ void k_clszero(const float* __restrict__ cls_tok) {
    int tid = threadIdx.x;
    if (blockIdx.x < N_IMG) {
        int b = blockIdx.x;
        float v = cls_tok[tid] + ((tid & 1) ? 1.0f : 0.0f);
        __nv_bfloat16 h = __float2bfloat16(v);
        size_t idx = (size_t)(b * S_TOK) * E_DIM + tid;
        g_x_h[idx] = h;
        g_x_l[idx] = __float2bfloat16(v - __bfloat162float(h));
    } else {
        for (int i = tid; i < N_IMG * E_DIM; i += blockDim.x) g_pooled[i] = 0.0f;
    }
}

// ======================= fused patchify + embed (FFMA) =======================
__global__ __launch_bounds__(256) void k_embed(const float* __restrict__ images,
                                               const float* __restrict__ lm_b) {
    float* smf = (float*)smraw;
    float* As = smf;               // [64][76]
    float* Bs = smf + 64 * KPAD;   // [76][128]
    const int b  = blockIdx.y;
    const int p0 = blockIdx.x * 64;
    const int tid = threadIdx.x;

    for (int i = tid; i < KPAD * E_DIM; i += 256) Bs[i] = g_lmwT[i];
    for (int i = tid; i < 64 * KPAD; i += 256) {
        int m = i / KPAD, k = i % KPAD;
        int p = p0 + m;
        float v = 0.0f;
        if (k < 75 && p < NPATCH) {
            int c = k / 25, r = k % 25, ph = r / 5, pw = r % 5;
            int ii = p / 51, jj = p % 51;
            v = images[((b * 3 + c) * 255 + (ii * 5 + ph)) * 255 + (jj * 5 + pw)];
        }
        As[i] = v;
    }
    __syncthreads();

    const int tx = tid & 15, ty = tid >> 4;
    float acc[4][8];
    #pragma unroll
    for (int i = 0; i < 4; i++)
        #pragma unroll
        for (int j = 0; j < 8; j++) acc[i][j] = 0.0f;

    #pragma unroll 1
    for (int k = 0; k < KPAD; k += 4) {
        float4 av[4];
        #pragma unroll
        for (int i = 0; i < 4; i++)
            av[i] = *(const float4*)&As[(ty * 4 + i) * KPAD + k];
        #pragma unroll
        for (int kk = 0; kk < 4; kk++) {
            float4 b0 = *(const float4*)&Bs[(k + kk) * E_DIM + tx * 4];
            float4 b1 = *(const float4*)&Bs[(k + kk) * E_DIM + 64 + tx * 4];
            float bb[8] = {b0.x, b0.y, b0.z, b0.w, b1.x, b1.y, b1.z, b1.w};
            #pragma unroll
            for (int i = 0; i < 4; i++) {
                float a = ((const float*)&av[i])[kk];
                #pragma unroll
                for (int j = 0; j < 8; j++) acc[i][j] += a * bb[j];
            }
        }
    }

    #pragma unroll
    for (int i = 0; i < 4; i++) {
        int p = p0 + ty * 4 + i;
        if (p >= NPATCH) continue;
        int s = 1 + p;
        size_t base = ((size_t)b * S_TOK + s) * E_DIM;
        #pragma unroll
        for (int half = 0; half < 2; half++) {
            int col = half * 64 + tx * 4;
            float vx = acc[i][half*4+0] + lm_b[col+0] + g_pe[s * E_DIM + col + 0];
            float vy = acc[i][half*4+1] + lm_b[col+1] + g_pe[s * E_DIM + col + 1];
            float vz = acc[i][half*4+2] + lm_b[col+2] + g_pe[s * E_DIM + col + 2];
            float vw = acc[i][half*4+3] + lm_b[col+3] + g_pe[s * E_DIM + col + 3];
            __nv_bfloat162 h0, l0, h1, l1;
            split2(vx, vy, &h0, &l0);
            split2(vz, vw, &h1, &l1);
            *(__nv_bfloat162*)&g_x_h[base + col]     = h0;
            *(__nv_bfloat162*)&g_x_h[base + col + 2] = h1;
            *(__nv_bfloat162*)&g_x_l[base + col]     = l0;
            *(__nv_bfloat162*)&g_x_l[base + col + 2] = l1;
        }
    }
}

// ======================= QKV GEMM (wmma bf16 split) =======================
// smem: Ah[128][136] Al Bh Bl (bf16) + bias tile [16][132] f32
#define QW_AH 0
#define QW_AL (128 * ASTR)
#define QW_BH (2 * 128 * ASTR)
#define QW_BL (3 * 128 * ASTR)
#define QW_NBF (4 * 128 * ASTR)                 // bf16 elements
#define QW_SMEM (QW_NBF * 2 + 16 * 132 * 4)

__global__ __launch_bounds__(256) void k_qkv_w(const float* __restrict__ b_in) {
    __nv_bfloat16* smb = (__nv_bfloat16*)smraw;
    float* sBias = (float*)(smraw + QW_NBF * 2);
    const int tid = threadIdx.x, wid = tid >> 5;
    const int m0 = blockIdx.x * 128, n0 = blockIdx.y * 128;

    stage136(smb + QW_AH, g_x_h + (size_t)m0 * E_DIM, tid);
    stage136(smb + QW_AL, g_x_l + (size_t)m0 * E_DIM, tid);
    stage136(smb + QW_BH, g_win_h + (size_t)n0 * E_DIM, tid);
    stage136(smb + QW_BL, g_win_l + (size_t)n0 * E_DIM, tid);
    for (int i = tid; i < 16 * 132; i += 256) sBias[i] = b_in[n0 + (i % 132 < 128 ? i % 132 : 0)];
    __syncthreads();

    const int wm = wid & 3, wn = wid >> 2;   // 4 m-tiles x 2 n-tiles; warp = 32 rows x 64 cols
    wmma::fragment<wmma::accumulator, 16, 16, 16, float> c[2][4];
    #pragma unroll
    for (int i = 0; i < 2; i++)
        #pragma unroll
        for (int j = 0; j < 4; j++)
            wmma::load_matrix_sync(c[i][j], &sBias[wn * 64 + j * 16], 132, wmma::mem_row_major);

    #pragma unroll
    for (int pass = 0; pass < 3; pass++) {
        const __nv_bfloat16* Ab = smb + (pass == 2 ? QW_AL : QW_AH);
        const __nv_bfloat16* Bb = smb + (pass == 1 ? QW_BL : QW_BH);
        #pragma unroll
        for (int k0 = 0; k0 < 128; k0 += 16) {
            wmma::fragment<wmma::matrix_a, 16, 16, 16, __nv_bfloat16, wmma::row_major> a[2];
            wmma::fragment<wmma::matrix_b, 16, 16, 16, __nv_bfloat16, wmma::col_major> b[4];
            #pragma unroll
            for (int i = 0; i < 2; i++)
                wmma::load_matrix_sync(a[i], &Ab[(wm * 32 + i * 16) * ASTR + k0], ASTR);
            #pragma unroll
            for (int j = 0; j < 4; j++)
                wmma::load_matrix_sync(b[j], &Bb[(wn * 64 + j * 16) * ASTR + k0], ASTR);
            #pragma unroll
            for (int i = 0; i < 2; i++)
                #pragma unroll
                for (int j = 0; j < 4; j++)
                    wmma::mma_sync(c[i][j], a[i], b[j], c[i][j]);
        }
    }

    #pragma unroll
    for (int i = 0; i < 2; i++)
        #pragma unroll
        for (int j = 0; j < 4; j++)
            wmma::store_matrix_sync(&g_qkv[(size_t)(m0 + wm * 32 + i * 16) * E3 + n0 + wn * 64 + j * 16],
                                    c[i][j], E3, wmma::mem_row_major);
}

// ======================= attention across images =======================
__global__ __launch_bounds__(512) void k_attn() {
    float* smf = (float*)smraw;      // [64][384] qkv for this token
    const int s = blockIdx.x, tid = threadIdx.x;

    for (int i = tid; i < 64 * 96; i += 512) {
        int b = i / 96, j = i % 96;
        ((float4*)smf)[i] = *(const float4*)&g_qkv[((size_t)b * S_TOK + s) * E3 + j * 4];
    }
    __syncthreads();

    const int h = tid >> 6, l = tid & 63;
    float q[16];
    {
        const float* qp = &smf[l * E3 + h * 16];
        #pragma unroll
        for (int d = 0; d < 16; d++) q[d] = qp[d] * 0.25f;
    }
    float sc[64];
    float mx = -1e30f;
    #pragma unroll
    for (int m = 0; m < 64; m++) {
        const float* kp = &smf[m * E3 + 128 + h * 16];
        float d0 = 0.f, d1 = 0.f, d2 = 0.f, d3 = 0.f;
        #pragma unroll
        for (int d = 0; d < 4; d++) {
            d0 += q[d]      * kp[d];
            d1 += q[4 + d]  * kp[4 + d];
            d2 += q[8 + d]  * kp[8 + d];
            d3 += q[12 + d] * kp[12 + d];
        }
        sc[m] = (d0 + d1) + (d2 + d3);
        mx = fmaxf(mx, sc[m]);
    }
    float sum = 0.f;
    #pragma unroll
    for (int m = 0; m < 64; m++) { sc[m] = expf(sc[m] - mx); sum += sc[m]; }
    float o[16];
    #pragma unroll
    for (int d = 0; d < 16; d++) o[d] = 0.f;
    #pragma unroll
    for (int m = 0; m < 64; m++) {
        const float w = sc[m];
        const float* vp = &smf[m * E3 + 256 + h * 16];
        #pragma unroll
        for (int d = 0; d < 16; d++) o[d] += w * vp[d];
    }
    const float inv = 1.0f / sum;
    size_t base = ((size_t)l * S_TOK + s) * E_DIM + h * 16;
    __nv_bfloat162* oh = (__nv_bfloat162*)&g_o_h[base];
    __nv_bfloat162* ol = (__nv_bfloat162*)&g_o_l[base];
    #pragma unroll
    for (int d2 = 0; d2 < 8; d2++) {
        __nv_bfloat162 hh, ll;
        split2(o[2*d2] * inv, o[2*d2+1] * inv, &hh, &ll);
        oh[d2] = hh;
        ol[d2] = ll;
    }
}

// ======================= out-proj GEMM + LN + pool (wmma) =======================
#define OW_AH 0
#define OW_AL (128 * ASTR)
#define OW_BH (2 * 128 * ASTR)
#define OW_BL (3 * 128 * ASTR)
#define OW_NBF (4 * 128 * ASTR)
#define OW_C    (OW_NBF * 2)                    // 128x132 f32
#define OW_BIAS (OW_C + 128 * 132 * 4)          // 16x132 f32
#define OW_MU   (OW_BIAS + 16 * 132 * 4)
#define OW_RSD  (OW_MU + 512)
#define OW_SMEM (OW_RSD + 512)

__global__ __launch_bounds__(256) void k_out_w(const float* __restrict__ b_out,
                                               const float* __restrict__ ln_g,
                                               const float* __restrict__ ln_b) {
    __nv_bfloat16* smb = (__nv_bfloat16*)smraw;
    float* Cs    = (float*)(smraw + OW_C);
    float* sBias = (float*)(smraw + OW_BIAS);
    float* sMu   = (float*)(smraw + OW_MU);
    float* sRsd  = (float*)(smraw + OW_RSD);
    const int tid = threadIdx.x, wid = tid >> 5;
    const int m0 = blockIdx.x * 128;

    stage136(smb + OW_AH, g_o_h + (size_t)m0 * E_DIM, tid);
    stage136(smb + OW_AL, g_o_l + (size_t)m0 * E_DIM, tid);
    stage136(smb + OW_BH, g_wout_h, tid);
    stage136(smb + OW_BL, g_wout_l, tid);
    for (int i = tid; i < 16 * 132; i += 256) sBias[i] = b_out[(i % 132 < 128 ? i % 132 : 0)];
    __syncthreads();

    const int wm = wid & 3, wn = wid >> 2;
    wmma::fragment<wmma::accumulator, 16, 16, 16, float> c[2][4];
    #pragma unroll
    for (int i = 0; i < 2; i++)
        #pragma unroll
        for (int j = 0; j < 4; j++)
            wmma::load_matrix_sync(c[i][j], &sBias[wn * 64 + j * 16], 132, wmma::mem_row_major);

    #pragma unroll
    for (int pass = 0; pass < 3; pass++) {
        const __nv_bfloat16* Ab = smb + (pass == 2 ? OW_AL : OW_AH);
        const __nv_bfloat16* Bb = smb + (pass == 1 ? OW_BL : OW_BH);
        #pragma unroll
        for (int k0 = 0; k0 < 128; k0 += 16) {
            wmma::fragment<wmma::matrix_a, 16, 16, 16, __nv_bfloat16, wmma::row_major> a[2];
            wmma::fragment<wmma::matrix_b, 16, 16, 16, __nv_bfloat16, wmma::col_major> b[4];
            #pragma unroll
            for (int i = 0; i < 2; i++)
                wmma::load_matrix_sync(a[i], &Ab[(wm * 32 + i * 16) * ASTR + k0], ASTR);
            #pragma unroll
            for (int j = 0; j < 4; j++)
                wmma::load_matrix_sync(b[j], &Bb[(wn * 64 + j * 16) * ASTR + k0], ASTR);
            #pragma unroll
            for (int i = 0; i < 2; i++)
                #pragma unroll
                for (int j = 0; j < 4; j++)
                    wmma::mma_sync(c[i][j], a[i], b[j], c[i][j]);
        }
    }

    #pragma unroll
    for (int i = 0; i < 2; i++)
        #pragma unroll
        for (int j = 0; j < 4; j++)
            wmma::store_matrix_sync(&Cs[(wm * 32 + i * 16) * 132 + wn * 64 + j * 16],
                                    c[i][j], 132, wmma::mem_row_major);
    __syncthreads();

    if (tid < 128) {
        const float* row = &Cs[tid * 132];
        float s1 = 0.f;
        #pragma unroll 8
        for (int j = 0; j < 128; j++) s1 += row[j];
        float mu = s1 * (1.0f / 128.0f);
        float s2 = 0.f;
        #pragma unroll 8
        for (int j = 0; j < 128; j++) { float d = row[j] - mu; s2 += d * d; }
        sMu[tid] = mu;
        sRsd[tid] = rsqrtf(s2 * (1.0f / 128.0f) + 1e-5f);
    }
    __syncthreads();

    {
        int col = tid & 127;
        int r = (tid >> 7) * 64;
        float gg = ln_g[col], bb = ln_b[col];
        int b0 = (m0 + r) / S_TOK;
        int boundary = (b0 + 1) * S_TOK - m0;
        float a0 = 0.f, a1 = 0.f;
        #pragma unroll 4
        for (int t = 0; t < 64; t++, r++) {
            float v = (Cs[r * 132 + col] - sMu[r]) * sRsd[r] * gg + bb;
            if (r < boundary) a0 += v; else a1 += v;
        }
        atomicAdd(&g_pooled[b0 * E_DIM + col], a0);
        if (a1 != 0.f || ((tid >> 7) * 64 + 63) >= boundary)
            if (b0 + 1 < N_IMG) atomicAdd(&g_pooled[(b0 + 1) * E_DIM + col], a1);
    }
}

// ======================= classifier head =======================
__global__ void k_head(const float* __restrict__ out_w,
                       const float* __restrict__ out_b,
                       float* __restrict__ out) {
    int b = blockIdx.x, tid = threadIdx.x;
    __shared__ float red[3][4];
    float p = g_pooled[b * E_DIM + tid] * (1.0f / (float)S_TOK);
    int lane = tid & 31, w = tid >> 5;
    #pragma unroll
    for (int c = 0; c < 3; c++) {
        float v = p * out_w[c * E_DIM + tid];
        #pragma unroll
        for (int off = 16; off; off >>= 1) v += __shfl_xor_sync(0xffffffffu, v, off);
        if (lane == 0) red[c][w] = v;
    }
    __syncthreads();
    if (tid < 3)
        out[b * 3 + tid] = red[tid][0] + red[tid][1] + red[tid][2] + red[tid][3] + out_b[tid];
}

// ======================= launch =======================
extern "C" void kernel_launch(void* const* d_in, const int* in_sizes, int n_in,
                              void* d_out, int out_size) {
    const float* images  = (const float*)d_in[0];
    const float* lm_w    = (const float*)d_in[1];
    const float* lm_b    = (const float*)d_in[2];
    const float* cls_tok = (const float*)d_in[3];
    const float* w_in    = (const float*)d_in[4];
    const float* b_in    = (const float*)d_in[5];
    const float* w_out   = (const float*)d_in[6];
    const float* b_out   = (const float*)d_in[7];
    const float* ln_g    = (const float*)d_in[8];
    const float* ln_b    = (const float*)d_in[9];
    const float* out_w   = (const float*)d_in[10];
    const float* out_b   = (const float*)d_in[11];
    float* out = (float*)d_out;

    const int SMEM_EMBED = (64 * KPAD + KPAD * E_DIM) * 4;
    const int SMEM_ATTN  = 64 * E3 * 4;

    cudaFuncSetAttribute(k_embed, cudaFuncAttributeMaxDynamicSharedMemorySize, SMEM_EMBED);
    cudaFuncSetAttribute(k_attn,  cudaFuncAttributeMaxDynamicSharedMemorySize, SMEM_ATTN);
    cudaFuncSetAttribute(k_qkv_w, cudaFuncAttributeMaxDynamicSharedMemorySize, QW_SMEM);
    cudaFuncSetAttribute(k_out_w, cudaFuncAttributeMaxDynamicSharedMemorySize, OW_SMEM);

    k_prep<<<96, 256>>>(lm_w, w_in, w_out);
    k_pe<<<S_TOK, 128>>>();
    k_clszero<<<N_IMG + 1, 128>>>(cls_tok);
    k_embed<<<dim3(41, N_IMG), 256, SMEM_EMBED>>>(images, lm_b);
    k_qkv_w<<<dim3(1301, 3), 256, QW_SMEM>>>(b_in);
    k_attn<<<S_TOK, 512, SMEM_ATTN>>>();
    k_out_w<<<1301, 256, OW_SMEM>>>(b_out, ln_g, ln_b);
    k_head<<<N_IMG, 128>>>(out_w, out_b, out);
}